// round 15
// baseline (speedup 1.0000x reference)
#include <cuda_runtime.h>
#include <cuda.h>
#include <cstdint>
#include <math.h>

// ---------------- scratch (no allocation allowed) ----------------
#define MAXN 256
#define MAXBLOCKS 8192

__device__ float g_partial[MAXBLOCKS * 2];
__device__ unsigned int g_count = 0;

// ---------------- tile config (1024 blocks) ----------------
#define TX 128
#define TY 16
#define BDX 32
#define BDY 8
#define NTHR (BDX * BDY)
#define TILE_BYTES (TX * TY * 4)
#define CULL_T 88.0f    // ex2.approx.ftz flushes to 0 beyond ~87.3 -> exact cull
#define LOG2E 1.4426950408889634f

__device__ __forceinline__ float ex2_approx(float x) {
    float r; asm("ex2.approx.ftz.f32 %0, %1;" : "=f"(r) : "f"(x)); return r;
}
__device__ __forceinline__ float rcp_approx(float x) {
    float r; asm("rcp.approx.ftz.f32 %0, %1;" : "=f"(r) : "f"(x)); return r;
}
__device__ __forceinline__ float sqrt_approx(float x) {
    float r; asm("sqrt.approx.ftz.f32 %0, %1;" : "=f"(r) : "f"(x)); return r;
}
__device__ __forceinline__ unsigned int smem_u32(const void* p) {
    return (unsigned int)__cvta_generic_to_shared(p);
}
__device__ __forceinline__ void cp_async16(unsigned int dst, const void* src) {
    asm volatile("cp.async.cg.shared.global [%0], [%1], 16;" :: "r"(dst), "l"(src));
}
__device__ __forceinline__ void st_cs_f2(float* p, float a, float b) {
    asm volatile("st.global.cs.v2.f32 [%0], {%1, %2};" :: "l"(p), "f"(a), "f"(b) : "memory");
}
__device__ __forceinline__ void tma_load_2d_cta(unsigned int smem_addr,
                                                const CUtensorMap* tmap,
                                                int cx, int cy, unsigned int mbar) {
    asm volatile(
        "cp.async.bulk.tensor.2d.shared::cta.global.tile.mbarrier::complete_tx::bytes "
        "[%0], [%1, {%2, %3}], [%4];"
        :: "r"(smem_addr), "l"(tmap), "r"(cx), "r"(cy), "r"(mbar) : "memory");
}
__device__ __forceinline__ unsigned int atom_acqrel_inc(unsigned int* p) {
    unsigned int v;
    asm volatile("atom.acq_rel.gpu.global.add.u32 %0, [%1], %2;"
                 : "=r"(v) : "l"(p), "r"(1u) : "memory");
    return v;
}

// ======================= shared epilogue/reduction code =======================
__device__ __forceinline__ void splat_and_finish(
    int tid, int x4, int y, int idx0, int idx1, bool ok0, bool ok1,
    int toff0, int toff1, const float* sh_h, const float* sh_k, const float* sh_s,
    const float4* s_p, int ns, float* gts, float* out,
    int nblocks, float invCount, int blin) {

    float fx = (float)x4, fy = (float)y;
    float m00 = 1e30f, m01 = 1e30f, m02 = 1e30f, m03 = 1e30f;
    float m10 = 1e30f, m11 = 1e30f, m12 = 1e30f, m13 = 1e30f;

    for (int i = 0; i < ns; i++) {
        float4 p = s_p[i];
        float s  = p.x;
        float d0 = fmaf(fx, s, -p.y);
        float d1 = d0 + s, d2 = d1 + s, d3 = d2 + s;
        float b0 = d0 * d0, b1 = d1 * d1, b2 = d2 * d2, b3 = d3 * d3;
        float e0 = fmaf(fy, s, -p.z);
        float e1 = fmaf(8.0f, s, e0);
        float a0 = e0 * e0, a1 = e1 * e1;
        m00 = fminf(m00, a0 + b0); m01 = fminf(m01, a0 + b1);
        m02 = fminf(m02, a0 + b2); m03 = fminf(m03, a0 + b3);
        m10 = fminf(m10, a1 + b0); m11 = fminf(m11, a1 + b1);
        m12 = fminf(m12, a1 + b2); m13 = fminf(m13, a1 + b3);
    }

    float lsum_hm = 0.0f, lsum_sm = 0.0f;
    if (ok0) {
        float4 h4 = *(const float4*)(sh_h + toff0);
        float4 k4 = *(const float4*)(sh_k + toff0);
        float4 s4 = *(const float4*)(sh_s + toff0);
        float4 g4;
        g4.x = ex2_approx(-m00); g4.y = ex2_approx(-m01);
        g4.z = ex2_approx(-m02); g4.w = ex2_approx(-m03);
        st_cs_f2(gts + idx0,     g4.x, g4.y);
        st_cs_f2(gts + idx0 + 2, g4.z, g4.w);
        float d;
        d = h4.x - g4.x; lsum_hm = fmaf(d * d, k4.x, lsum_hm);
        d = h4.y - g4.y; lsum_hm = fmaf(d * d, k4.y, lsum_hm);
        d = h4.z - g4.z; lsum_hm = fmaf(d * d, k4.z, lsum_hm);
        d = h4.w - g4.w; lsum_hm = fmaf(d * d, k4.w, lsum_hm);
        lsum_sm = fmaf(s4.x, s4.x, lsum_sm); lsum_sm = fmaf(s4.y, s4.y, lsum_sm);
        lsum_sm = fmaf(s4.z, s4.z, lsum_sm); lsum_sm = fmaf(s4.w, s4.w, lsum_sm);
    }
    if (ok1) {
        float4 h4 = *(const float4*)(sh_h + toff1);
        float4 k4 = *(const float4*)(sh_k + toff1);
        float4 s4 = *(const float4*)(sh_s + toff1);
        float4 g4;
        g4.x = ex2_approx(-m10); g4.y = ex2_approx(-m11);
        g4.z = ex2_approx(-m12); g4.w = ex2_approx(-m13);
        st_cs_f2(gts + idx1,     g4.x, g4.y);
        st_cs_f2(gts + idx1 + 2, g4.z, g4.w);
        float d;
        d = h4.x - g4.x; lsum_hm = fmaf(d * d, k4.x, lsum_hm);
        d = h4.y - g4.y; lsum_hm = fmaf(d * d, k4.y, lsum_hm);
        d = h4.z - g4.z; lsum_hm = fmaf(d * d, k4.z, lsum_hm);
        d = h4.w - g4.w; lsum_hm = fmaf(d * d, k4.w, lsum_hm);
        lsum_sm = fmaf(s4.x, s4.x, lsum_sm); lsum_sm = fmaf(s4.y, s4.y, lsum_sm);
        lsum_sm = fmaf(s4.z, s4.z, lsum_sm); lsum_sm = fmaf(s4.w, s4.w, lsum_sm);
    }

    __shared__ float wh[NTHR / 32];
    __shared__ float ws[NTHR / 32];
    int lane = tid & 31;
    int wid  = tid >> 5;
#pragma unroll
    for (int off = 16; off > 0; off >>= 1) {
        lsum_hm += __shfl_down_sync(0xFFFFFFFFu, lsum_hm, off);
        lsum_sm += __shfl_down_sync(0xFFFFFFFFu, lsum_sm, off);
    }
    if (lane == 0) { wh[wid] = lsum_hm; ws[wid] = lsum_sm; }
    __syncthreads();

    __shared__ int isLast;
    if (tid == 0) {
        float th = 0.0f, ts = 0.0f;
#pragma unroll
        for (int i = 0; i < NTHR / 32; i++) { th += wh[i]; ts += ws[i]; }
        g_partial[2 * blin + 0] = th;
        g_partial[2 * blin + 1] = ts;
        unsigned int v = atom_acqrel_inc(&g_count);
        isLast = (v == (unsigned int)(nblocks - 1));
    }
    __syncthreads();

    if (isLast) {
        volatile float* vp = g_partial;
        float sh = 0.0f, ss = 0.0f;
        for (int i = tid; i < nblocks; i += NTHR) {
            sh += vp[2 * i + 0];
            ss += vp[2 * i + 1];
        }
        __shared__ float rh[NTHR];
        __shared__ float rs[NTHR];
        rh[tid] = sh; rs[tid] = ss;
        __syncthreads();
        for (int sft = NTHR / 2; sft > 0; sft >>= 1) {
            if (tid < sft) { rh[tid] += rh[tid + sft]; rs[tid] += rs[tid + sft]; }
            __syncthreads();
        }
        if (tid == 0) {
            out[0] = rs[0] * invCount;   // scale_loss = mean(sm^2)
            out[1] = rh[0] * invCount;   // hm_loss    = mean((hm-gt)^2 * mask)
            g_count = 0;                 // reset for next graph replay
        }
    }
}

// ---- phase A with block-cooperative EXACT dominance prune ----
// pass1: per-center L (min-corner arg), hi (max-corner arg); U = block-min(hi).
// pass2: keep only L <= min(U, CULL_T). Any dropped center is either
// everywhere-dominated by the U-attaining center or flushes to 0 -> exact.
__device__ __forceinline__ int phase_a_prune(
    int tid, int b, int x0, int y0, int base, int H, int W, int N,
    const float* sm, const float* gr, const int* centers,
    float4* s_pc, unsigned int* s_U, float4* s_p, int* s_ns) {

    float g  = __ldg(&gr[b]);
    float rg = rcp_approx(g);
    float t  = 0.2f * rg;                       // PR_MIN / gr
    float fx0 = (float)x0;
    float fx1 = (float)min(x0 + TX - 1, W - 1);
    float fy0 = (float)y0;
    float fy1 = (float)min(y0 + TY - 1, H - 1);
    const int2* cptr = (const int2*)centers;

    // pass 1
    for (int i = tid; i < N; i += NTHR) {
        int2 c = __ldg(&cptr[b * N + i]);
        int cy = min(max(c.x, 0), H - 1);       // reference clamps both to H-1
        int cx = min(max(c.y, 0), H - 1);
        float smv = __ldg(&sm[base + cy * W + cx]);
        float relu = fmaxf(smv, 0.0f);
        float size = t + (relu * 0.2f) * rg;    // PR_MIN/gr + relu*RES/gr
        float inv = rcp_approx(2.0f * size * size);
        float fcx = (float)cx, fcy = (float)cy;
        float ddx = fmaxf(fmaxf(fx0 - fcx, fcx - fx1), 0.0f);
        float ddy = fmaxf(fmaxf(fy0 - fcy, fcy - fy1), 0.0f);
        float L = (ddx * ddx + ddy * ddy) * inv;
        float mdx = fmaxf(fcx - fx0, fx1 - fcx);
        float mdy = fmaxf(fcy - fy0, fy1 - fcy);
        float hi = (mdx * mdx + mdy * mdy) * inv;
        s_pc[i] = make_float4(inv, fcx, fcy, L);
        atomicMin(s_U, __float_as_uint(hi));    // positive floats: bit-order == order
    }
    __syncthreads();

    // pass 2
    float U = fminf(__uint_as_float(*s_U), CULL_T);
    for (int i = tid; i < N; i += NTHR) {
        float4 p = s_pc[i];
        if (p.w <= U) {
            float s = sqrt_approx(p.x * LOG2E);
            int k = atomicAdd(s_ns, 1);         // order-free: fmin is commutative
            s_p[k] = make_float4(s, p.y * s, p.z * s, 0.0f);
        }
    }
    __syncthreads();
    return *s_ns;
}

// ======================= TMA kernel =======================
__global__ __launch_bounds__(NTHR)
void fused_tma(const __grid_constant__ CUtensorMap tm_h,
               const __grid_constant__ CUtensorMap tm_s,
               const __grid_constant__ CUtensorMap tm_k,
               const float* __restrict__ sm,
               const float* __restrict__ gr,
               const int*   __restrict__ centers,
               float* __restrict__ gts,    // only 8-byte aligned (d_out + 2)
               float* __restrict__ out,
               int H, int W, int N, int nblocks, float invCount) {
    int b  = blockIdx.z;
    int x0 = blockIdx.x * TX;
    int y0 = blockIdx.y * TY;
    int tid = threadIdx.y * BDX + threadIdx.x;

    __shared__ __align__(128) float sh_h[TY * TX];
    __shared__ __align__(128) float sh_s[TY * TX];
    __shared__ __align__(128) float sh_k[TY * TX];
    __shared__ float4 s_pc[MAXN];       // {inv, cx, cy, L}
    __shared__ float4 s_p[MAXN];        // survivors {s, s*cx, s*cy, 0}
    __shared__ unsigned int s_U;
    __shared__ int s_ns;
    __shared__ __align__(8) unsigned long long s_mbar;

    int x4 = x0 + threadIdx.x * 4;
    int y  = y0 + threadIdx.y;
    int base = b * H * W;
    int idx0 = base + y * W + x4;
    int idx1 = idx0 + BDY * W;
    bool ok0 = (x4 + 3) < W && y < H;
    bool ok1 = (x4 + 3) < W && (y + BDY) < H;
    int toff0 = threadIdx.y * TX + threadIdx.x * 4;
    int toff1 = toff0 + BDY * TX;

    if (tid == 0) {
        s_ns = 0;
        s_U  = 0x7F7FFFFFu;   // +FLT_MAX bits
        unsigned int mb = smem_u32(&s_mbar);
        asm volatile("mbarrier.init.shared.b64 [%0], 1;" :: "r"(mb));
        asm volatile("fence.proxy.async.shared::cta;" ::: "memory");
        asm volatile("mbarrier.arrive.expect_tx.shared.b64 _, [%0], %1;"
                     :: "r"(mb), "r"(3u * TILE_BYTES) : "memory");
        int rowbase = b * H + y0;
        tma_load_2d_cta(smem_u32(sh_h), &tm_h, x0, rowbase, mb);
        tma_load_2d_cta(smem_u32(sh_s), &tm_s, x0, rowbase, mb);
        tma_load_2d_cta(smem_u32(sh_k), &tm_k, x0, rowbase, mb);
    }
    __syncthreads();

    int ns = phase_a_prune(tid, b, x0, y0, base, H, W, N,
                           sm, gr, centers, s_pc, &s_U, s_p, &s_ns);

    {
        unsigned int mb = smem_u32(&s_mbar);
        asm volatile(
            "{\n\t.reg .pred P;\n\t"
            "WL%=:\n\t"
            "mbarrier.try_wait.parity.acquire.cta.shared::cta.b64 P, [%0], 0;\n\t"
            "@P bra WD%=;\n\t"
            "bra WL%=;\n\t"
            "WD%=:\n\t}"
            :: "r"(mb) : "memory");
    }

    int blin = (b * gridDim.y + blockIdx.y) * gridDim.x + blockIdx.x;
    splat_and_finish(tid, x4, y, idx0, idx1, ok0, ok1, toff0, toff1,
                     sh_h, sh_k, sh_s, s_p, ns, gts, out, nblocks, invCount, blin);
}

// ======================= cp.async fallback kernel =======================
__global__ __launch_bounds__(NTHR)
void fused_cpasync(const float* __restrict__ hm,
                   const float* __restrict__ sm,
                   const float* __restrict__ mask,
                   const float* __restrict__ gr,
                   const int*   __restrict__ centers,
                   float* __restrict__ gts,
                   float* __restrict__ out,
                   int H, int W, int N, int nblocks, float invCount) {
    int b  = blockIdx.z;
    int x0 = blockIdx.x * TX;
    int y0 = blockIdx.y * TY;
    int tid = threadIdx.y * BDX + threadIdx.x;

    __shared__ __align__(128) float sh_h[TY * TX];
    __shared__ __align__(128) float sh_s[TY * TX];
    __shared__ __align__(128) float sh_k[TY * TX];
    __shared__ float4 s_pc[MAXN];
    __shared__ float4 s_p[MAXN];
    __shared__ unsigned int s_U;
    __shared__ int s_ns;

    int x4 = x0 + threadIdx.x * 4;
    int y  = y0 + threadIdx.y;
    int base = b * H * W;
    int idx0 = base + y * W + x4;
    int idx1 = idx0 + BDY * W;
    bool ok0 = (x4 + 3) < W && y < H;
    bool ok1 = (x4 + 3) < W && (y + BDY) < H;
    int toff0 = threadIdx.y * TX + threadIdx.x * 4;
    int toff1 = toff0 + BDY * TX;
    {
        unsigned int h0 = smem_u32(sh_h), k0 = smem_u32(sh_k), s0 = smem_u32(sh_s);
        if (ok0) {
            cp_async16(h0 + toff0 * 4, hm + idx0);
            cp_async16(k0 + toff0 * 4, mask + idx0);
            cp_async16(s0 + toff0 * 4, sm + idx0);
        }
        if (ok1) {
            cp_async16(h0 + toff1 * 4, hm + idx1);
            cp_async16(k0 + toff1 * 4, mask + idx1);
            cp_async16(s0 + toff1 * 4, sm + idx1);
        }
        asm volatile("cp.async.commit_group;" ::: "memory");
    }

    if (tid == 0) { s_ns = 0; s_U = 0x7F7FFFFFu; }
    __syncthreads();

    int ns = phase_a_prune(tid, b, x0, y0, base, H, W, N,
                           sm, gr, centers, s_pc, &s_U, s_p, &s_ns);

    asm volatile("cp.async.wait_group 0;" ::: "memory");

    int blin = (b * gridDim.y + blockIdx.y) * gridDim.x + blockIdx.x;
    splat_and_finish(tid, x4, y, idx0, idx1, ok0, ok1, toff0, toff1,
                     sh_h, sh_k, sh_s, s_p, ns, gts, out, nblocks, invCount, blin);
}

// ======================= host =======================
typedef CUresult (*EncodeTiledFn)(
    CUtensorMap*, CUtensorMapDataType, cuuint32_t, void*,
    const cuuint64_t*, const cuuint64_t*, const cuuint32_t*, const cuuint32_t*,
    CUtensorMapInterleave, CUtensorMapSwizzle, CUtensorMapL2promotion,
    CUtensorMapFloatOOBfill);

extern "C" void kernel_launch(void* const* d_in, const int* in_sizes, int n_in,
                              void* d_out, int out_size) {
    const float* hm      = (const float*)d_in[0];
    const float* sm      = (const float*)d_in[1];
    const float* gr      = (const float*)d_in[2];
    const float* mask    = (const float*)d_in[3];
    const int*   centers = (const int*)  d_in[4];

    int B  = in_sizes[2];
    int HW = in_sizes[0] / B;
    int H  = 1;
    while ((long long)H * H < (long long)HW) H++;   // 512
    int W  = HW / H;
    int N  = in_sizes[4] / (2 * B);

    float* out = (float*)d_out;
    float* gts = out + (out_size - (size_t)B * HW); // tuple: [sl, hl, gts...]

    dim3 grid((W + TX - 1) / TX, (H + TY - 1) / TY, B);
    dim3 block(BDX, BDY);
    int nblocks = grid.x * grid.y * grid.z;
    float invCount = 1.0f / ((float)B * (float)HW);

    bool use_tma = false;
    CUtensorMap tm_h, tm_s, tm_k;
    void* fp = nullptr;
    cudaDriverEntryPointQueryResult qr;
    if (cudaGetDriverEntryPointByVersion("cuTensorMapEncodeTiled", &fp, 12000,
                                         cudaEnableDefault, &qr) == cudaSuccess &&
        fp != nullptr) {
        EncodeTiledFn enc = (EncodeTiledFn)fp;
        cuuint64_t dims[2]    = {(cuuint64_t)W, (cuuint64_t)((long long)B * H)};
        cuuint64_t strides[1] = {(cuuint64_t)W * 4};
        cuuint32_t box[2]     = {TX, TY};
        cuuint32_t estr[2]    = {1, 1};
        CUresult r1 = enc(&tm_h, CU_TENSOR_MAP_DATA_TYPE_FLOAT32, 2, (void*)hm,
                          dims, strides, box, estr, CU_TENSOR_MAP_INTERLEAVE_NONE,
                          CU_TENSOR_MAP_SWIZZLE_NONE, CU_TENSOR_MAP_L2_PROMOTION_L2_128B,
                          CU_TENSOR_MAP_FLOAT_OOB_FILL_NONE);
        CUresult r2 = enc(&tm_s, CU_TENSOR_MAP_DATA_TYPE_FLOAT32, 2, (void*)sm,
                          dims, strides, box, estr, CU_TENSOR_MAP_INTERLEAVE_NONE,
                          CU_TENSOR_MAP_SWIZZLE_NONE, CU_TENSOR_MAP_L2_PROMOTION_L2_128B,
                          CU_TENSOR_MAP_FLOAT_OOB_FILL_NONE);
        CUresult r3 = enc(&tm_k, CU_TENSOR_MAP_DATA_TYPE_FLOAT32, 2, (void*)mask,
                          dims, strides, box, estr, CU_TENSOR_MAP_INTERLEAVE_NONE,
                          CU_TENSOR_MAP_SWIZZLE_NONE, CU_TENSOR_MAP_L2_PROMOTION_L2_128B,
                          CU_TENSOR_MAP_FLOAT_OOB_FILL_NONE);
        use_tma = (r1 == CUDA_SUCCESS && r2 == CUDA_SUCCESS && r3 == CUDA_SUCCESS);
    }

    if (use_tma) {
        fused_tma<<<grid, block>>>(tm_h, tm_s, tm_k, sm, gr, centers, gts, out,
                                   H, W, N, nblocks, invCount);
    } else {
        fused_cpasync<<<grid, block>>>(hm, sm, mask, gr, centers, gts, out,
                                       H, W, N, nblocks, invCount);
    }
}

// round 16
// speedup vs baseline: 1.0931x; 1.0931x over previous
#include <cuda_runtime.h>
#include <cstdint>
#include <math.h>

// ---------------- scratch (no allocation allowed) ----------------
#define MAXN 128
#define MAXBLOCKS 8192

__device__ float g_partial[MAXBLOCKS * 2];
__device__ unsigned int g_count = 0;

// ---------------- tile config: 2 tiles per block, 512 blocks ----------------
#define TX 128
#define TY 16
#define BDX 32
#define BDY 8
#define NTHR (BDX * BDY)
#define NTILES 2
#define TILE_F (TY * TX)                  // floats per array per tile (2048)
// ex2.approx.ftz flushes 2^-t to exactly 0 for t > ~126; cull in log2 units.
#define CULL_L2 127.0f
#define LOG2E 1.4426950408889634f

// dynamic smem layout (floats/bytes)
#define SM_TILES_B (NTILES * 3 * TILE_F * 4)          // 49152
#define SM_PAR_B   (MAXN * 16)                        // 2048
#define SM_SRV_B   (NTILES * MAXN * 16)               // 4096
#define SM_DYN_B   (SM_TILES_B + SM_PAR_B + SM_SRV_B) // 55296

__device__ __forceinline__ float ex2_approx(float x) {
    float r; asm("ex2.approx.ftz.f32 %0, %1;" : "=f"(r) : "f"(x)); return r;
}
__device__ __forceinline__ float rcp_approx(float x) {
    float r; asm("rcp.approx.ftz.f32 %0, %1;" : "=f"(r) : "f"(x)); return r;
}
__device__ __forceinline__ float sqrt_approx(float x) {
    float r; asm("sqrt.approx.ftz.f32 %0, %1;" : "=f"(r) : "f"(x)); return r;
}
__device__ __forceinline__ unsigned int smem_u32(const void* p) {
    return (unsigned int)__cvta_generic_to_shared(p);
}
__device__ __forceinline__ void cp_async16(unsigned int dst, const void* src) {
    asm volatile("cp.async.cg.shared.global [%0], [%1], 16;" :: "r"(dst), "l"(src));
}
__device__ __forceinline__ void st_cs_f2(float* p, float a, float b) {
    asm volatile("st.global.cs.v2.f32 [%0], {%1, %2};" :: "l"(p), "f"(a), "f"(b) : "memory");
}
__device__ __forceinline__ unsigned int atom_acqrel_inc(unsigned int* p) {
    unsigned int v;
    asm volatile("atom.acq_rel.gpu.global.add.u32 %0, [%1], %2;"
                 : "=r"(v) : "l"(p), "r"(1u) : "memory");
    return v;
}

// Two-tile pipelined kernel:
//  entry : issue cp.async for BOTH tiles (2 commit groups)
//  phaseP: per-center params (cx, cy, s, s^2) ONCE per block (tile-independent)
//  per tile t: ALU-only cull from smem params -> survivors; wait_group (1-t);
//              splat + EX2 epilogue + loss accumulate
//  finish: one reduction/atomic per block (512 total)
__global__ __launch_bounds__(NTHR)
void fused2(const float* __restrict__ hm,
            const float* __restrict__ sm,
            const float* __restrict__ mask,
            const float* __restrict__ gr,
            const int*   __restrict__ centers,
            float* __restrict__ gts,    // only 8-byte aligned (d_out + 2)
            float* __restrict__ out,
            int H, int W, int N, int nblocks, float invCount) {
    extern __shared__ __align__(128) char dsm[];
    float*  sh_tiles = (float*)dsm;                                // [stage][3][TILE_F]
    float4* s_par    = (float4*)(dsm + SM_TILES_B);                // [MAXN] {cx,cy,s,s2}
    float4* s_srv    = (float4*)(dsm + SM_TILES_B + SM_PAR_B);     // [stage][MAXN]
    __shared__ int s_ns[NTILES];
    __shared__ float wh[NTHR / 32], ws[NTHR / 32];
    __shared__ int isLast;

    int b     = blockIdx.z;
    int y0    = blockIdx.y * TY;
    int xbase = blockIdx.x * (NTILES * TX);
    int tid   = threadIdx.y * BDX + threadIdx.x;
    int y     = y0 + threadIdx.y;                 // rows y and y+BDY
    int base  = b * H * W;
    int toff0 = threadIdx.y * TX + threadIdx.x * 4;
    int toff1 = toff0 + BDY * TX;

    // ---- entry: issue cp.async for both tiles, one commit group each ----
#pragma unroll
    for (int t = 0; t < NTILES; t++) {
        int x0 = xbase + t * TX;
        int x4 = x0 + threadIdx.x * 4;
        int i0 = base + y * W + x4;
        int i1 = i0 + BDY * W;
        float* st_h = sh_tiles + (t * 3 + 0) * TILE_F;
        float* st_s = sh_tiles + (t * 3 + 1) * TILE_F;
        float* st_k = sh_tiles + (t * 3 + 2) * TILE_F;
        if ((x4 + 3) < W && y < H) {
            cp_async16(smem_u32(st_h) + toff0 * 4, hm + i0);
            cp_async16(smem_u32(st_s) + toff0 * 4, sm + i0);
            cp_async16(smem_u32(st_k) + toff0 * 4, mask + i0);
        }
        if ((x4 + 3) < W && (y + BDY) < H) {
            cp_async16(smem_u32(st_h) + toff1 * 4, hm + i1);
            cp_async16(smem_u32(st_s) + toff1 * 4, sm + i1);
            cp_async16(smem_u32(st_k) + toff1 * 4, mask + i1);
        }
        asm volatile("cp.async.commit_group;" ::: "memory");
    }

    if (tid == 0) { s_ns[0] = 0; s_ns[1] = 0; }

    // ---- phase P: per-center params ONCE per block (tile-independent) ----
    {
        float g  = __ldg(&gr[b]);
        float rg = rcp_approx(g);
        float t0 = 0.2f * rg;                       // PR_MIN / gr
        const int2* cptr = (const int2*)centers;
        for (int i = tid; i < N; i += NTHR) {
            int2 c = __ldg(&cptr[b * N + i]);
            int cy = min(max(c.x, 0), H - 1);       // reference clamps both to H-1
            int cx = min(max(c.y, 0), H - 1);
            float smv = __ldg(&sm[base + cy * W + cx]);
            float relu = fmaxf(smv, 0.0f);
            float size = t0 + (relu * 0.2f) * rg;   // PR_MIN/gr + relu*RES/gr
            float inv = rcp_approx(2.0f * size * size);
            float s2 = inv * LOG2E;                 // log2-units scale^2
            float s  = sqrt_approx(s2);
            s_par[i] = make_float4((float)cx, (float)cy, s, s2);
        }
    }
    __syncthreads();

    float lsum_hm = 0.0f, lsum_sm = 0.0f;

#pragma unroll
    for (int t = 0; t < NTILES; t++) {
        int x0 = xbase + t * TX;
        int x4 = x0 + threadIdx.x * 4;
        float fx0 = (float)x0;
        float fx1 = (float)min(x0 + TX - 1, W - 1);
        float fy0 = (float)y0;
        float fy1 = (float)min(y0 + TY - 1, H - 1);

        // ---- cull tile t: pure ALU over smem-resident params ----
        float4* srv = s_srv + t * MAXN;
        for (int i = tid; i < N; i += NTHR) {
            float4 p = s_par[i];
            float ddx = fmaxf(fmaxf(fx0 - p.x, p.x - fx1), 0.0f);
            float ddy = fmaxf(fmaxf(fy0 - p.y, p.y - fy1), 0.0f);
            float d2min = ddx * ddx + ddy * ddy;
            if (d2min * p.w <= CULL_L2) {           // exact: flushes to 0 otherwise
                int k = atomicAdd(&s_ns[t], 1);     // order-free: fmin commutative
                srv[k] = make_float4(p.z, p.x * p.z, p.y * p.z, 0.0f);
            }
        }
        __syncthreads();
        int ns = s_ns[t];

        // ---- splat ----
        float fx = (float)x4, fy = (float)y;
        float m00 = 1e30f, m01 = 1e30f, m02 = 1e30f, m03 = 1e30f;
        float m10 = 1e30f, m11 = 1e30f, m12 = 1e30f, m13 = 1e30f;
        for (int i = 0; i < ns; i++) {
            float4 p = srv[i];
            float s  = p.x;
            float d0 = fmaf(fx, s, -p.y);
            float d1 = d0 + s, d2 = d1 + s, d3 = d2 + s;
            float b0 = d0 * d0, b1 = d1 * d1, b2 = d2 * d2, b3 = d3 * d3;
            float e0 = fmaf(fy, s, -p.z);
            float e1 = fmaf(8.0f, s, e0);
            float a0 = e0 * e0, a1 = e1 * e1;
            m00 = fminf(m00, a0 + b0); m01 = fminf(m01, a0 + b1);
            m02 = fminf(m02, a0 + b2); m03 = fminf(m03, a0 + b3);
            m10 = fminf(m10, a1 + b0); m11 = fminf(m11, a1 + b1);
            m12 = fminf(m12, a1 + b2); m13 = fminf(m13, a1 + b3);
        }

        // ---- wait for THIS tile's data (later tiles stay in flight) ----
        if (t == 0) { asm volatile("cp.async.wait_group 1;" ::: "memory"); }
        else       { asm volatile("cp.async.wait_group 0;" ::: "memory"); }

        const float* st_h = sh_tiles + (t * 3 + 0) * TILE_F;
        const float* st_s = sh_tiles + (t * 3 + 1) * TILE_F;
        const float* st_k = sh_tiles + (t * 3 + 2) * TILE_F;
        int i0 = base + y * W + x4;
        int i1 = i0 + BDY * W;

        if ((x4 + 3) < W && y < H) {
            float4 h4 = *(const float4*)(st_h + toff0);
            float4 s4 = *(const float4*)(st_s + toff0);
            float4 k4 = *(const float4*)(st_k + toff0);
            float4 g4;
            g4.x = ex2_approx(-m00); g4.y = ex2_approx(-m01);
            g4.z = ex2_approx(-m02); g4.w = ex2_approx(-m03);
            st_cs_f2(gts + i0,     g4.x, g4.y);
            st_cs_f2(gts + i0 + 2, g4.z, g4.w);
            float d;
            d = h4.x - g4.x; lsum_hm = fmaf(d * d, k4.x, lsum_hm);
            d = h4.y - g4.y; lsum_hm = fmaf(d * d, k4.y, lsum_hm);
            d = h4.z - g4.z; lsum_hm = fmaf(d * d, k4.z, lsum_hm);
            d = h4.w - g4.w; lsum_hm = fmaf(d * d, k4.w, lsum_hm);
            lsum_sm = fmaf(s4.x, s4.x, lsum_sm); lsum_sm = fmaf(s4.y, s4.y, lsum_sm);
            lsum_sm = fmaf(s4.z, s4.z, lsum_sm); lsum_sm = fmaf(s4.w, s4.w, lsum_sm);
        }
        if ((x4 + 3) < W && (y + BDY) < H) {
            float4 h4 = *(const float4*)(st_h + toff1);
            float4 s4 = *(const float4*)(st_s + toff1);
            float4 k4 = *(const float4*)(st_k + toff1);
            float4 g4;
            g4.x = ex2_approx(-m10); g4.y = ex2_approx(-m11);
            g4.z = ex2_approx(-m12); g4.w = ex2_approx(-m13);
            st_cs_f2(gts + i1,     g4.x, g4.y);
            st_cs_f2(gts + i1 + 2, g4.z, g4.w);
            float d;
            d = h4.x - g4.x; lsum_hm = fmaf(d * d, k4.x, lsum_hm);
            d = h4.y - g4.y; lsum_hm = fmaf(d * d, k4.y, lsum_hm);
            d = h4.z - g4.z; lsum_hm = fmaf(d * d, k4.z, lsum_hm);
            d = h4.w - g4.w; lsum_hm = fmaf(d * d, k4.w, lsum_hm);
            lsum_sm = fmaf(s4.x, s4.x, lsum_sm); lsum_sm = fmaf(s4.y, s4.y, lsum_sm);
            lsum_sm = fmaf(s4.z, s4.z, lsum_sm); lsum_sm = fmaf(s4.w, s4.w, lsum_sm);
        }
    }

    // ---- one reduction per block (512 total) ----
    int lane = tid & 31;
    int wid  = tid >> 5;
#pragma unroll
    for (int off = 16; off > 0; off >>= 1) {
        lsum_hm += __shfl_down_sync(0xFFFFFFFFu, lsum_hm, off);
        lsum_sm += __shfl_down_sync(0xFFFFFFFFu, lsum_sm, off);
    }
    if (lane == 0) { wh[wid] = lsum_hm; ws[wid] = lsum_sm; }
    __syncthreads();

    if (tid == 0) {
        float th = 0.0f, ts = 0.0f;
#pragma unroll
        for (int i = 0; i < NTHR / 32; i++) { th += wh[i]; ts += ws[i]; }
        int blin = (b * gridDim.y + blockIdx.y) * gridDim.x + blockIdx.x;
        g_partial[2 * blin + 0] = th;
        g_partial[2 * blin + 1] = ts;
        unsigned int v = atom_acqrel_inc(&g_count);
        isLast = (v == (unsigned int)(nblocks - 1));
    }
    __syncthreads();

    if (isLast) {
        volatile float* vp = g_partial;
        float sh = 0.0f, ss = 0.0f;
        for (int i = tid; i < nblocks; i += NTHR) {
            sh += vp[2 * i + 0];
            ss += vp[2 * i + 1];
        }
        // reuse tile smem for the final reduction scratch
        float* rh = sh_tiles;
        float* rs = sh_tiles + NTHR;
        rh[tid] = sh; rs[tid] = ss;
        __syncthreads();
        for (int sft = NTHR / 2; sft > 0; sft >>= 1) {
            if (tid < sft) { rh[tid] += rh[tid + sft]; rs[tid] += rs[tid + sft]; }
            __syncthreads();
        }
        if (tid == 0) {
            out[0] = rs[0] * invCount;   // scale_loss = mean(sm^2)
            out[1] = rh[0] * invCount;   // hm_loss    = mean((hm-gt)^2 * mask)
            g_count = 0;                 // reset for next graph replay
        }
    }
}

extern "C" void kernel_launch(void* const* d_in, const int* in_sizes, int n_in,
                              void* d_out, int out_size) {
    const float* hm      = (const float*)d_in[0];
    const float* sm      = (const float*)d_in[1];
    const float* gr      = (const float*)d_in[2];
    const float* mask    = (const float*)d_in[3];
    const int*   centers = (const int*)  d_in[4];

    int B  = in_sizes[2];                 // ground_resolution: [B]
    int HW = in_sizes[0] / B;             // pred_hm: [B,1,H,W]
    int H  = 1;
    while ((long long)H * H < (long long)HW) H++;   // 512
    int W  = HW / H;
    int N  = in_sizes[4] / (2 * B);       // centers: [B,N,2]

    float* out = (float*)d_out;
    float* gts = out + (out_size - (size_t)B * HW); // tuple: [sl, hl, gts...]

    dim3 grid((W + NTILES * TX - 1) / (NTILES * TX), (H + TY - 1) / TY, B);
    dim3 block(BDX, BDY);
    int nblocks = grid.x * grid.y * grid.z;

    static bool attr_done = false;
    if (!attr_done) {
        cudaFuncSetAttribute(fused2, cudaFuncAttributeMaxDynamicSharedMemorySize,
                             SM_DYN_B);
        attr_done = true;
    }
    fused2<<<grid, block, SM_DYN_B>>>(hm, sm, mask, gr, centers, gts, out,
                                      H, W, N, nblocks,
                                      1.0f / ((float)B * (float)HW));
}